// round 15
// baseline (speedup 1.0000x reference)
#include <cuda_runtime.h>
#include <cuda_fp16.h>
#include <cstdint>

// Problem constants (fixed by setup_inputs)
#define NNODES 10000
#define EEDGES 320000
#define DDIM   128
#define HDIM   1024
#define KDIM   4096     // 32 * 128 (only first half of W1 rows matter)

// ---------------- scratch (no allocation allowed) ----------------
__device__ __align__(128) __half g_Ah [NNODES * KDIM];        // fp16(M)  82 MB
__device__ __align__(128) __half g_Hp [NNODES * 2 * HDIM];    // [10000,2048]: z=0 cols 0-1023, z=1 cols 1024-2047
__device__ __align__(128) __half g_W1T[HDIM * KDIM];          // fp16(W1[:4096]^T) [1024][4096]
__device__ __align__(128) __half g_W2D[DDIM * 2 * HDIM];      // fp16((a1*W2*a2)^T) duplicated [128][2048]
__device__ __align__(128) float  g_bias[DDIM];
__device__ __align__(128) float  g_Mv [NNODES * DDIM];

// ---------------- helpers ----------------
__device__ __forceinline__ uint32_t smem_u32(const void* p) {
    uint32_t a;
    asm("{ .reg .u64 t; cvta.to.shared.u64 t, %1; cvt.u32.u64 %0, t; }" : "=r"(a) : "l"(p));
    return a;
}

__device__ __forceinline__ void cp_async16(uint32_t dst, const void* src) {
    asm volatile("cp.async.cg.shared.global [%0], [%1], 16;" :: "r"(dst), "l"(src) : "memory");
}
__device__ __forceinline__ void cp_commit() {
    asm volatile("cp.async.commit_group;" ::: "memory");
}
template<int N>
__device__ __forceinline__ void cp_wait() {
    asm volatile("cp.async.wait_group %0;" :: "n"(N) : "memory");
}

__device__ __forceinline__ void ldmx4(unsigned& r0, unsigned& r1, unsigned& r2, unsigned& r3,
                                      uint32_t addr) {
    asm volatile("ldmatrix.sync.aligned.m8n8.x4.shared.b16 {%0,%1,%2,%3}, [%4];"
                 : "=r"(r0), "=r"(r1), "=r"(r2), "=r"(r3) : "r"(addr));
}

__device__ __forceinline__ void mma_f16(float c[4], const unsigned a[4], const unsigned b[2]) {
    asm volatile(
        "mma.sync.aligned.m16n8k16.row.col.f32.f16.f16.f32 "
        "{%0,%1,%2,%3}, {%4,%5,%6,%7}, {%8,%9}, {%0,%1,%2,%3};\n"
        : "+f"(c[0]), "+f"(c[1]), "+f"(c[2]), "+f"(c[3])
        : "r"(a[0]), "r"(a[1]), "r"(a[2]), "r"(a[3]),
          "r"(b[0]), "r"(b[1]));
}

// ---------------- prep kernels ----------------
// convert one 2048-column half of M to fp16 (matches split-K slice z)
__global__ void conv_f16_half_kernel(const float* __restrict__ in, __half* __restrict__ out,
                                     int half)
{
    constexpr int CH = NNODES * 512;      // float4 chunks in one half
    const int base = half * 2048;
    int stride = gridDim.x * blockDim.x;
    for (int i = blockIdx.x * blockDim.x + threadIdx.x; i < CH; i += stride) {
        int row = i >> 9;
        int c   = (i & 511) << 2;
        float4 v = *(const float4*)(in + (size_t)row * KDIM + base + c);
        __half2 h0 = __floats2half2_rn(v.x, v.y);
        __half2 h1 = __floats2half2_rn(v.z, v.w);
        uint2 u = make_uint2(*reinterpret_cast<unsigned*>(&h0),
                             *reinterpret_cast<unsigned*>(&h1));
        *(uint2*)(out + (size_t)row * KDIM + base + c) = u;
    }
}

// W1 [4096,1024] f32 -> W1T [1024][4096] fp16
__global__ void transpose_w1_kernel(const float* __restrict__ W1, __half* __restrict__ W1T)
{
    __shared__ float t[32][33];
    int k0 = blockIdx.x * 32, n0 = blockIdx.y * 32;
    int tx = threadIdx.x, ty = threadIdx.y;
    #pragma unroll
    for (int i = 0; i < 4; i++)
        t[ty + i * 8][tx] = W1[(size_t)(k0 + ty + i * 8) * HDIM + n0 + tx];
    __syncthreads();
    #pragma unroll
    for (int i = 0; i < 4; i++)
        W1T[(size_t)(n0 + ty + i * 8) * KDIM + k0 + tx] = __float2half_rn(t[tx][ty + i * 8]);
}

// W2 [1024,128] f32 -> W2D [128][2048] fp16 duplicated, scaled by a1[h]*a2[d]
__global__ void fold_w2d_kernel(const float* __restrict__ W2,
                                const float* __restrict__ g1, const float* __restrict__ rv1,
                                const float* __restrict__ g2, const float* __restrict__ rv2,
                                __half* __restrict__ W2D)
{
    __shared__ float t[32][33];
    int h0 = blockIdx.x * 32, d0 = blockIdx.y * 32;
    int tx = threadIdx.x, ty = threadIdx.y;
    #pragma unroll
    for (int i = 0; i < 4; i++)
        t[ty + i * 8][tx] = W2[(size_t)(h0 + ty + i * 8) * DDIM + d0 + tx];
    __syncthreads();
    float a1 = g1[h0 + tx] * rsqrtf(rv1[h0 + tx] + 1e-5f);
    #pragma unroll
    for (int i = 0; i < 4; i++) {
        int d = d0 + ty + i * 8;
        float a2 = g2[d] * rsqrtf(rv2[d] + 1e-5f);
        __half v = __float2half_rn(a1 * a2 * t[tx][ty + i * 8]);
        W2D[(size_t)d * 2 * HDIM + h0 + tx] = v;          // copy 0 (vs p0)
        W2D[(size_t)d * 2 * HDIM + HDIM + h0 + tx] = v;   // copy 1 (vs p1)
    }
}

// parallel bias fold: one block per d, 256-thread reduction over h
__global__ void fold_bias_kernel(const float* __restrict__ W2,
                                 const float* __restrict__ b1, const float* __restrict__ g1,
                                 const float* __restrict__ be1, const float* __restrict__ rm1,
                                 const float* __restrict__ rv1,
                                 const float* __restrict__ b2, const float* __restrict__ g2,
                                 const float* __restrict__ be2, const float* __restrict__ rm2,
                                 const float* __restrict__ rv2,
                                 float* __restrict__ biasOut)
{
    __shared__ float red[8];
    int d = blockIdx.x;
    int tid = threadIdx.x;
    float s = 0.f;
    for (int h = tid; h < HDIM; h += 256) {
        float a1 = g1[h] * rsqrtf(rv1[h] + 1e-5f);
        float c1 = (b1[h] - rm1[h]) * a1 + be1[h];
        s += c1 * W2[h * DDIM + d];
    }
    #pragma unroll
    for (int o = 16; o > 0; o >>= 1) s += __shfl_down_sync(0xffffffffu, s, o);
    if ((tid & 31) == 0) red[tid >> 5] = s;
    __syncthreads();
    if (tid == 0) {
        float t = 0.f;
        #pragma unroll
        for (int i = 0; i < 8; i++) t += red[i];
        float a2 = g2[d] * rsqrtf(rv2[d] + 1e-5f);
        biasOut[d] = (t + b2[d] - rm2[d]) * a2 + be2[d];
    }
}

// ---------------- fp16 GEMM: cp.async + ldmatrix (R10 mainloop) -------------
// C[M,:] = A[M, zsel*kLen : (zsel+1)*kLen] @ B[:, zsel*kLen : ...]^T slice.
// A row stride lda, B row stride ldb, C row stride ldc, C column offset cOff.
// 256 threads = 8 warps (2M x 4N), warp tile 64x32, K-tile 64, 3 stages,
// launch_bounds(256,2) -> 2 CTAs/SM. One cp.async group committed EVERY
// iteration (tail-safe); single leading barrier per iteration.
// EPI=0: C fp16 at C + row*ldc + cOff + col.
// EPI=1: C fp32 = relu(acc + bias[col]).
template<int BM, int BN, int EPI>
__global__ void __launch_bounds__(256, 2)
gemm_f16_kernel(const __half* __restrict__ A, int lda,
                const __half* __restrict__ B, int ldb,
                void* __restrict__ Cv, int ldc, int cOff,
                int Mrows, int kLen,
                const float* __restrict__ bias, int zsel)
{
    constexpr int KT = 64, STAGES = 3;
    constexpr int WM = BM / 2, WN = BN / 4;
    constexpr int MT = WM / 16, NTN = WN / 8;      // NTN must be even
    constexpr int LDH = KT + 8;                    // 72 halves per smem row
    constexpr int A_HL = BM * LDH;
    constexpr int B_HL = BN * LDH;
    constexpr int ACH = BM * (KT / 8);
    constexpr int BCH = BN * (KT / 8);

    extern __shared__ __align__(16) __half smem[];
    __half* As = smem;                             // [STAGES][BM][LDH]
    __half* Bs = smem + STAGES * A_HL;             // [STAGES][BN][LDH]
    const uint32_t asb = smem_u32(As);
    const uint32_t bsb = smem_u32(Bs);

    const int tid   = threadIdx.x;
    const int lane  = tid & 31;
    const int warp  = tid >> 5;
    const int warpM = warp >> 2;                   // 0..1
    const int warpN = warp & 3;                    // 0..3
    const int bM = blockIdx.y * BM;
    const int bN = blockIdx.x * BN;
    const int NT = kLen / KT;

    // BOTH operands offset by the split-K slice (the R14 bug dropped Bp's)
    const __half* Ap = A + (size_t)zsel * kLen;
    const __half* Bp = B + (size_t)zsel * kLen;

    const int aRow = lane & 15;
    const int aK   = (lane >> 4) << 3;
    const int bRow = (lane & 7) + ((lane >> 4) << 3);
    const int bK   = ((lane >> 3) & 1) << 3;

    float acc[MT][NTN][4];
    #pragma unroll
    for (int i = 0; i < MT; i++)
        #pragma unroll
        for (int j = 0; j < NTN; j++)
            #pragma unroll
            for (int k = 0; k < 4; k++) acc[i][j][k] = 0.f;

    auto load_stage = [&](int s, int kt) {
        const uint32_t aDst = asb + s * A_HL * 2;
        #pragma unroll
        for (int i = 0; i < ACH / 256; i++) {
            int idx = tid + i * 256;
            int row = idx >> 3;                    // 8 chunks per row
            int c   = idx & 7;
            int gr  = bM + row; if (gr >= Mrows) gr = Mrows - 1;
            cp_async16(aDst + (row * LDH + c * 8) * 2,
                       Ap + (size_t)gr * lda + kt * KT + c * 8);
        }
        const uint32_t bDst = bsb + s * B_HL * 2;
        #pragma unroll
        for (int i = 0; i < BCH / 256; i++) {
            int idx = tid + i * 256;
            int row = idx >> 3;
            int c   = idx & 7;
            cp_async16(bDst + (row * LDH + c * 8) * 2,
                       Bp + (size_t)(bN + row) * ldb + kt * KT + c * 8);
        }
    };

    load_stage(0, 0); cp_commit();
    load_stage(1, 1); cp_commit();

    int s = 0;
    for (int kt = 0; kt < NT; kt++) {
        cp_wait<STAGES - 2>();
        __syncthreads();   // stage s ready; all warps done with stage s+2
        if (kt + 2 < NT)
            load_stage((s + 2 >= STAGES) ? s - 1 : s + 2, kt + 2);
        cp_commit();       // always (tail-safe)

        const uint32_t aBase = asb + s * A_HL * 2;
        const uint32_t bBase = bsb + s * B_HL * 2;
        #pragma unroll
        for (int kk = 0; kk < KT / 16; kk++) {
            const int k0 = kk * 16;
            unsigned af[MT][4];
            #pragma unroll
            for (int mt = 0; mt < MT; mt++) {
                uint32_t ad = aBase + ((warpM * WM + mt * 16 + aRow) * LDH + k0 + aK) * 2;
                ldmx4(af[mt][0], af[mt][1], af[mt][2], af[mt][3], ad);
            }
            unsigned bf[NTN][2];
            #pragma unroll
            for (int pr = 0; pr < NTN / 2; pr++) {
                uint32_t bd = bBase + ((warpN * WN + pr * 16 + bRow) * LDH + k0 + bK) * 2;
                unsigned r0, r1, r2, r3;
                ldmx4(r0, r1, r2, r3, bd);
                bf[pr * 2][0] = r0; bf[pr * 2][1] = r1;
                bf[pr * 2 + 1][0] = r2; bf[pr * 2 + 1][1] = r3;
            }
            #pragma unroll
            for (int mt = 0; mt < MT; mt++)
                #pragma unroll
                for (int nt = 0; nt < NTN; nt++)
                    mma_f16(acc[mt][nt], af[mt], bf[nt]);
        }
        if (++s == STAGES) s = 0;
    }

    // ---- epilogue ----
    #pragma unroll
    for (int mt = 0; mt < MT; mt++) {
        int rowBase = bM + warpM * WM + mt * 16 + (lane >> 2);
        #pragma unroll
        for (int half = 0; half < 2; half++) {
            int row = rowBase + half * 8;
            if (row >= Mrows) continue;
            #pragma unroll
            for (int nt = 0; nt < NTN; nt++) {
                int col = bN + warpN * WN + nt * 8 + ((lane & 3) << 1);
                float v0 = acc[mt][nt][half * 2 + 0];
                float v1 = acc[mt][nt][half * 2 + 1];
                if (EPI == 1) {
                    v0 = fmaxf(v0 + bias[col],     0.f);
                    v1 = fmaxf(v1 + bias[col + 1], 0.f);
                    *(float2*)((float*)Cv + (size_t)row * ldc + cOff + col) =
                        make_float2(v0, v1);
                } else {
                    __half2 h = __floats2half2_rn(v0, v1);
                    *(__half2*)((__half*)Cv + (size_t)row * ldc + cOff + col) = h;
                }
            }
        }
    }
}

// ---------------- scatter: out[e] = Mv[src[e]] - M[rev[e]] ----------------
__global__ void scatter_kernel(const float* __restrict__ Mv, const float* __restrict__ M,
                               const int* __restrict__ ei, const int* __restrict__ rv,
                               float* __restrict__ out)
{
    const bool ei64 = ((ei[1] | ei[3] | ei[5] | ei[7]) == 0);
    const bool rv64 = ((rv[1] | rv[3] | rv[5] | rv[7]) == 0);
    int e = blockIdx.x * 8 + (threadIdx.x >> 5);
    if (e >= EEDGES) return;
    int lane = threadIdx.x & 31;
    int s = ei64 ? (int)((const long long*)ei)[e] : ei[e];
    int r = rv64 ? (int)((const long long*)rv)[e] : rv[e];
    float4 a = *(const float4*)(Mv + (size_t)s * DDIM + (lane << 2));
    float4 b = *(const float4*)(M  + (size_t)r * DDIM + (lane << 2));
    *(float4*)(out + (size_t)e * DDIM + (lane << 2)) =
        make_float4(a.x - b.x, a.y - b.y, a.z - b.z, a.w - b.w);
}

// ---------------- launch ----------------
extern "C" void kernel_launch(void* const* d_in, const int* in_sizes, int n_in,
                              void* d_out, int out_size)
{
    // Inputs: M, edge_index, rev_index, [dim_size], W1,b1,g1,be1,rm1,rv1,W2,b2,g2,be2,rm2,rv2
    int off = (n_in >= 16) ? 1 : 0;
    const float* M   = (const float*)d_in[0];
    const int*   ei  = (const int*)  d_in[1];
    const int*   rev = (const int*)  d_in[2];
    const float* W1  = (const float*)d_in[3 + off];
    const float* b1  = (const float*)d_in[4 + off];
    const float* g1v = (const float*)d_in[5 + off];
    const float* be1 = (const float*)d_in[6 + off];
    const float* rm1 = (const float*)d_in[7 + off];
    const float* rv1 = (const float*)d_in[8 + off];
    const float* W2  = (const float*)d_in[9 + off];
    const float* b2  = (const float*)d_in[10 + off];
    const float* g2v = (const float*)d_in[11 + off];
    const float* be2 = (const float*)d_in[12 + off];
    const float* rm2 = (const float*)d_in[13 + off];
    const float* rv2 = (const float*)d_in[14 + off];
    float* out = (float*)d_out;

    __half *pAh, *pHp, *pW1T, *pW2D;
    float  *pBias, *pMv;
    cudaGetSymbolAddress((void**)&pAh,   g_Ah);
    cudaGetSymbolAddress((void**)&pHp,   g_Hp);
    cudaGetSymbolAddress((void**)&pW1T,  g_W1T);
    cudaGetSymbolAddress((void**)&pW2D,  g_W2D);
    cudaGetSymbolAddress((void**)&pBias, g_bias);
    cudaGetSymbolAddress((void**)&pMv,   g_Mv);

    static cudaStream_t s1 = nullptr;
    static cudaEvent_t evFork = nullptr, evW = nullptr, ev1 = nullptr;
    if (!s1) {
        cudaStreamCreateWithFlags(&s1, cudaStreamNonBlocking);
        cudaEventCreateWithFlags(&evFork, cudaEventDisableTiming);
        cudaEventCreateWithFlags(&evW,    cudaEventDisableTiming);
        cudaEventCreateWithFlags(&ev1,    cudaEventDisableTiming);
    }

    constexpr int SMEM1 = 3 * (128 + 128) * 72 * 2;   // 110,592 B (x2 CTAs = 221KB)
    constexpr int SMEM2 = 3 * (64  + 128) * 72 * 2;   //  82,944 B
    cudaFuncSetAttribute((const void*)gemm_f16_kernel<128, 128, 0>,
                         cudaFuncAttributeMaxDynamicSharedMemorySize, SMEM1);
    cudaFuncSetAttribute((const void*)gemm_f16_kernel<64, 128, 1>,
                         cudaFuncAttributeMaxDynamicSharedMemorySize, SMEM2);

    // ---- fork side stream (R12 ordering) ----
    cudaEventRecord(evFork, 0);
    cudaStreamWaitEvent(s1, evFork, 0);

    // s1: weight preps, conv half 1, GEMM1 z=1
    transpose_w1_kernel<<<dim3(KDIM / 32, HDIM / 32), dim3(32, 8), 0, s1>>>(W1, pW1T);
    cudaEventRecord(evW, s1);          // W1T ready (needed by z=0 on s0)
    fold_w2d_kernel<<<dim3(HDIM / 32, DDIM / 32), dim3(32, 8), 0, s1>>>(
        W2, g1v, rv1, g2v, rv2, pW2D);
    fold_bias_kernel<<<DDIM, 256, 0, s1>>>(
        W2, b1, g1v, be1, rm1, rv1, b2, g2v, be2, rm2, rv2, pBias);
    conv_f16_half_kernel<<<1024, 256, 0, s1>>>(M, pAh, 1);
    gemm_f16_kernel<128, 128, 0>
        <<<dim3(HDIM / 128, (NNODES + 127) / 128), 256, SMEM1, s1>>>(
            pAh, KDIM, pW1T, KDIM, pHp, 2 * HDIM, HDIM, NNODES, KDIM / 2, nullptr, 1);
    cudaEventRecord(ev1, s1);

    // s0: conv half 0, GEMM1 z=0
    conv_f16_half_kernel<<<1024, 256>>>(M, pAh, 0);
    cudaStreamWaitEvent(0, evW, 0);
    gemm_f16_kernel<128, 128, 0>
        <<<dim3(HDIM / 128, (NNODES + 127) / 128), 256, SMEM1>>>(
            pAh, KDIM, pW1T, KDIM, pHp, 2 * HDIM, 0, NNODES, KDIM / 2, nullptr, 0);

    // join: s0 waits for s1's chain
    cudaStreamWaitEvent(0, ev1, 0);

    // GEMM2 (K=2048, fused split-K reduce): Mv = relu([p0|p1] @ W2D^T + bias)
    gemm_f16_kernel<64, 128, 1>
        <<<dim3(DDIM / 128, (NNODES + 63) / 64), 256, SMEM2>>>(
            pHp, 2 * HDIM, pW2D, 2 * HDIM, pMv, DDIM, 0, NNODES, 2 * HDIM, pBias, 0);

    // out[e] = Mv[src[e]] - M[rev[e]]
    scatter_kernel<<<EEDGES / 8, 256>>>(pMv, M, ei, rev, out);
}

// round 16
// speedup vs baseline: 2.1401x; 2.1401x over previous
#include <cuda_runtime.h>
#include <cuda_fp16.h>
#include <cstdint>

// Problem constants (fixed by setup_inputs)
#define NNODES 10000
#define EEDGES 320000
#define DDIM   128
#define HDIM   1024
#define KDIM   4096     // 32 * 128 (only first half of W1 rows matter)

// ---------------- scratch (no allocation allowed) ----------------
// KEY INSIGHT: no activation between the two linear layers (BN is affine in
// eval mode) -> whole MLP = relu(x @ Wc + bc), Wc = W1[:4096] @ (a1*W2*a2).
__device__ __align__(128) __half g_Ah [NNODES * KDIM];      // fp16(M)         82 MB
__device__ __align__(128) __half g_W1h[KDIM * HDIM];        // fp16(W1[:4096])  8 MB
__device__ __align__(128) __half g_W2T[DDIM * HDIM];        // fp16((a1*W2*a2)^T) [128][1024]
__device__ __align__(128) __half g_WcT[DDIM * KDIM];        // fp16(Wc^T) [128][4096] 1 MB
__device__ __align__(128) float  g_bias[DDIM];
__device__ __align__(128) float  g_MvP[2 * NNODES * DDIM];  // split-K fp32 partials 10 MB
__device__ __align__(128) float  g_Mv [NNODES * DDIM];

// ---------------- helpers ----------------
__device__ __forceinline__ uint32_t smem_u32(const void* p) {
    uint32_t a;
    asm("{ .reg .u64 t; cvta.to.shared.u64 t, %1; cvt.u32.u64 %0, t; }" : "=r"(a) : "l"(p));
    return a;
}

__device__ __forceinline__ void cp_async16(uint32_t dst, const void* src) {
    asm volatile("cp.async.cg.shared.global [%0], [%1], 16;" :: "r"(dst), "l"(src) : "memory");
}
__device__ __forceinline__ void cp_commit() {
    asm volatile("cp.async.commit_group;" ::: "memory");
}
template<int N>
__device__ __forceinline__ void cp_wait() {
    asm volatile("cp.async.wait_group %0;" :: "n"(N) : "memory");
}

__device__ __forceinline__ void ldmx4(unsigned& r0, unsigned& r1, unsigned& r2, unsigned& r3,
                                      uint32_t addr) {
    asm volatile("ldmatrix.sync.aligned.m8n8.x4.shared.b16 {%0,%1,%2,%3}, [%4];"
                 : "=r"(r0), "=r"(r1), "=r"(r2), "=r"(r3) : "r"(addr));
}

__device__ __forceinline__ void mma_f16(float c[4], const unsigned a[4], const unsigned b[2]) {
    asm volatile(
        "mma.sync.aligned.m16n8k16.row.col.f32.f16.f16.f32 "
        "{%0,%1,%2,%3}, {%4,%5,%6,%7}, {%8,%9}, {%0,%1,%2,%3};\n"
        : "+f"(c[0]), "+f"(c[1]), "+f"(c[2]), "+f"(c[3])
        : "r"(a[0]), "r"(a[1]), "r"(a[2]), "r"(a[3]),
          "r"(b[0]), "r"(b[1]));
}

// ---------------- prep kernels ----------------
// generic fp32 -> fp16 conversion (n4 float4 chunks)
__global__ void conv_f16_kernel(const float* __restrict__ in, __half* __restrict__ out, int n4)
{
    int stride = gridDim.x * blockDim.x;
    for (int i = blockIdx.x * blockDim.x + threadIdx.x; i < n4; i += stride) {
        float4 v = ((const float4*)in)[i];
        __half2 h0 = __floats2half2_rn(v.x, v.y);
        __half2 h1 = __floats2half2_rn(v.z, v.w);
        uint2 u = make_uint2(*reinterpret_cast<unsigned*>(&h0),
                             *reinterpret_cast<unsigned*>(&h1));
        ((uint2*)out)[i] = u;
    }
}

// W2 [1024,128] f32 -> W2T [128][1024] fp16, scaled by a1[h]*a2[d]
__global__ void fold_w2t_kernel(const float* __restrict__ W2,
                                const float* __restrict__ g1, const float* __restrict__ rv1,
                                const float* __restrict__ g2, const float* __restrict__ rv2,
                                __half* __restrict__ W2T)
{
    __shared__ float t[32][33];
    int h0 = blockIdx.x * 32, d0 = blockIdx.y * 32;
    int tx = threadIdx.x, ty = threadIdx.y;
    #pragma unroll
    for (int i = 0; i < 4; i++)
        t[ty + i * 8][tx] = W2[(size_t)(h0 + ty + i * 8) * DDIM + d0 + tx];
    __syncthreads();
    float a1 = g1[h0 + tx] * rsqrtf(rv1[h0 + tx] + 1e-5f);
    #pragma unroll
    for (int i = 0; i < 4; i++) {
        int d = d0 + ty + i * 8;
        float a2 = g2[d] * rsqrtf(rv2[d] + 1e-5f);
        W2T[(size_t)d * HDIM + h0 + tx] = __float2half_rn(a1 * a2 * t[tx][ty + i * 8]);
    }
}

// parallel bias fold: one block per d, 256-thread reduction over h
__global__ void fold_bias_kernel(const float* __restrict__ W2,
                                 const float* __restrict__ b1, const float* __restrict__ g1,
                                 const float* __restrict__ be1, const float* __restrict__ rm1,
                                 const float* __restrict__ rv1,
                                 const float* __restrict__ b2, const float* __restrict__ g2,
                                 const float* __restrict__ be2, const float* __restrict__ rm2,
                                 const float* __restrict__ rv2,
                                 float* __restrict__ biasOut)
{
    __shared__ float red[8];
    int d = blockIdx.x;
    int tid = threadIdx.x;
    float s = 0.f;
    for (int h = tid; h < HDIM; h += 256) {
        float a1 = g1[h] * rsqrtf(rv1[h] + 1e-5f);
        float c1 = (b1[h] - rm1[h]) * a1 + be1[h];
        s += c1 * W2[h * DDIM + d];
    }
    #pragma unroll
    for (int o = 16; o > 0; o >>= 1) s += __shfl_down_sync(0xffffffffu, s, o);
    if ((tid & 31) == 0) red[tid >> 5] = s;
    __syncthreads();
    if (tid == 0) {
        float t = 0.f;
        #pragma unroll
        for (int i = 0; i < 8; i++) t += red[i];
        float a2 = g2[d] * rsqrtf(rv2[d] + 1e-5f);
        biasOut[d] = (t + b2[d] - rm2[d]) * a2 + be2[d];
    }
}

// split-K reduce + bias + relu: Mv = relu(p0 + p1 + bias[col])  (fp32)
__global__ void reduce_bias_relu_kernel(const float* __restrict__ p,
                                        const float* __restrict__ bias,
                                        float* __restrict__ out)
{
    constexpr int N4 = NNODES * DDIM / 4;
    int stride = gridDim.x * blockDim.x;
    for (int i = blockIdx.x * blockDim.x + threadIdx.x; i < N4; i += stride) {
        float4 a = ((const float4*)p)[i];
        float4 b = ((const float4*)p)[i + N4];
        float4 bs = ((const float4*)bias)[i & 31];   // DDIM/4 = 32 chunks per row
        float4 r;
        r.x = fmaxf(a.x + b.x + bs.x, 0.f);
        r.y = fmaxf(a.y + b.y + bs.y, 0.f);
        r.z = fmaxf(a.z + b.z + bs.z, 0.f);
        r.w = fmaxf(a.w + b.w + bs.w, 0.f);
        ((float4*)out)[i] = r;
    }
}

// ---------------- fp16 GEMM: cp.async + ldmatrix (R10 mainloop) -------------
// C[M,:] = A[M, zsel*kLen : (zsel+1)*kLen] @ B[:, zsel*kLen : ...]^T slice.
// A row stride lda, B row stride ldb, C row stride ldc, C column offset cOff.
// 256 threads = 8 warps (2M x 4N), warp tile 64x32, K-tile 64, 3 stages,
// launch_bounds(256,2) -> 2 CTAs/SM. One cp.async group committed EVERY
// iteration (tail-safe); single leading barrier per iteration.
// EPI=0: C fp16. EPI=1: C fp32 = relu(acc + bias[col]).
// EPI=2: C fp32 raw partial at Cv + zsel*Mrows*ldc.
template<int BM, int BN, int EPI>
__global__ void __launch_bounds__(256, 2)
gemm_f16_kernel(const __half* __restrict__ A, int lda,
                const __half* __restrict__ B, int ldb,
                void* __restrict__ Cv, int ldc, int cOff,
                int Mrows, int kLen,
                const float* __restrict__ bias, int zsel)
{
    constexpr int KT = 64, STAGES = 3;
    constexpr int WM = BM / 2, WN = BN / 4;
    constexpr int MT = WM / 16, NTN = WN / 8;      // NTN must be even
    constexpr int LDH = KT + 8;                    // 72 halves per smem row
    constexpr int A_HL = BM * LDH;
    constexpr int B_HL = BN * LDH;
    constexpr int ACH = BM * (KT / 8);
    constexpr int BCH = BN * (KT / 8);

    extern __shared__ __align__(16) __half smem[];
    __half* As = smem;                             // [STAGES][BM][LDH]
    __half* Bs = smem + STAGES * A_HL;             // [STAGES][BN][LDH]
    const uint32_t asb = smem_u32(As);
    const uint32_t bsb = smem_u32(Bs);

    const int tid   = threadIdx.x;
    const int lane  = tid & 31;
    const int warp  = tid >> 5;
    const int warpM = warp >> 2;                   // 0..1
    const int warpN = warp & 3;                    // 0..3
    const int bM = blockIdx.y * BM;
    const int bN = blockIdx.x * BN;
    const int NT = kLen / KT;

    // both operands offset by the split-K slice
    const __half* Ap = A + (size_t)zsel * kLen;
    const __half* Bp = B + (size_t)zsel * kLen;

    const int aRow = lane & 15;
    const int aK   = (lane >> 4) << 3;
    const int bRow = (lane & 7) + ((lane >> 4) << 3);
    const int bK   = ((lane >> 3) & 1) << 3;

    float acc[MT][NTN][4];
    #pragma unroll
    for (int i = 0; i < MT; i++)
        #pragma unroll
        for (int j = 0; j < NTN; j++)
            #pragma unroll
            for (int k = 0; k < 4; k++) acc[i][j][k] = 0.f;

    auto load_stage = [&](int s, int kt) {
        const uint32_t aDst = asb + s * A_HL * 2;
        #pragma unroll
        for (int i = 0; i < ACH / 256; i++) {
            int idx = tid + i * 256;
            int row = idx >> 3;                    // 8 chunks per row
            int c   = idx & 7;
            int gr  = bM + row; if (gr >= Mrows) gr = Mrows - 1;
            cp_async16(aDst + (row * LDH + c * 8) * 2,
                       Ap + (size_t)gr * lda + kt * KT + c * 8);
        }
        const uint32_t bDst = bsb + s * B_HL * 2;
        #pragma unroll
        for (int i = 0; i < BCH / 256; i++) {
            int idx = tid + i * 256;
            int row = idx >> 3;
            int c   = idx & 7;
            cp_async16(bDst + (row * LDH + c * 8) * 2,
                       Bp + (size_t)(bN + row) * ldb + kt * KT + c * 8);
        }
    };

    load_stage(0, 0); cp_commit();
    load_stage(1, 1); cp_commit();

    int s = 0;
    for (int kt = 0; kt < NT; kt++) {
        cp_wait<STAGES - 2>();
        __syncthreads();   // stage s ready; all warps done with stage s+2
        if (kt + 2 < NT)
            load_stage((s + 2 >= STAGES) ? s - 1 : s + 2, kt + 2);
        cp_commit();       // always (tail-safe)

        const uint32_t aBase = asb + s * A_HL * 2;
        const uint32_t bBase = bsb + s * B_HL * 2;
        #pragma unroll
        for (int kk = 0; kk < KT / 16; kk++) {
            const int k0 = kk * 16;
            unsigned af[MT][4];
            #pragma unroll
            for (int mt = 0; mt < MT; mt++) {
                uint32_t ad = aBase + ((warpM * WM + mt * 16 + aRow) * LDH + k0 + aK) * 2;
                ldmx4(af[mt][0], af[mt][1], af[mt][2], af[mt][3], ad);
            }
            unsigned bf[NTN][2];
            #pragma unroll
            for (int pr = 0; pr < NTN / 2; pr++) {
                uint32_t bd = bBase + ((warpN * WN + pr * 16 + bRow) * LDH + k0 + bK) * 2;
                unsigned r0, r1, r2, r3;
                ldmx4(r0, r1, r2, r3, bd);
                bf[pr * 2][0] = r0; bf[pr * 2][1] = r1;
                bf[pr * 2 + 1][0] = r2; bf[pr * 2 + 1][1] = r3;
            }
            #pragma unroll
            for (int mt = 0; mt < MT; mt++)
                #pragma unroll
                for (int nt = 0; nt < NTN; nt++)
                    mma_f16(acc[mt][nt], af[mt], bf[nt]);
        }
        if (++s == STAGES) s = 0;
    }

    // ---- epilogue ----
    #pragma unroll
    for (int mt = 0; mt < MT; mt++) {
        int rowBase = bM + warpM * WM + mt * 16 + (lane >> 2);
        #pragma unroll
        for (int half = 0; half < 2; half++) {
            int row = rowBase + half * 8;
            if (row >= Mrows) continue;
            #pragma unroll
            for (int nt = 0; nt < NTN; nt++) {
                int col = bN + warpN * WN + nt * 8 + ((lane & 3) << 1);
                float v0 = acc[mt][nt][half * 2 + 0];
                float v1 = acc[mt][nt][half * 2 + 1];
                if (EPI == 1) {
                    v0 = fmaxf(v0 + bias[col],     0.f);
                    v1 = fmaxf(v1 + bias[col + 1], 0.f);
                    *(float2*)((float*)Cv + (size_t)row * ldc + cOff + col) =
                        make_float2(v0, v1);
                } else if (EPI == 2) {
                    float* Cp = (float*)Cv + (size_t)zsel * Mrows * ldc;
                    *(float2*)(Cp + (size_t)row * ldc + cOff + col) =
                        make_float2(v0, v1);
                } else {
                    __half2 h = __floats2half2_rn(v0, v1);
                    *(__half2*)((__half*)Cv + (size_t)row * ldc + cOff + col) = h;
                }
            }
        }
    }
}

// ---------------- scatter: out[e] = Mv[src[e]] - M[rev[e]] ----------------
__global__ void scatter_kernel(const float* __restrict__ Mv, const float* __restrict__ M,
                               const int* __restrict__ ei, const int* __restrict__ rv,
                               float* __restrict__ out)
{
    const bool ei64 = ((ei[1] | ei[3] | ei[5] | ei[7]) == 0);
    const bool rv64 = ((rv[1] | rv[3] | rv[5] | rv[7]) == 0);
    int e = blockIdx.x * 8 + (threadIdx.x >> 5);
    if (e >= EEDGES) return;
    int lane = threadIdx.x & 31;
    int s = ei64 ? (int)((const long long*)ei)[e] : ei[e];
    int r = rv64 ? (int)((const long long*)rv)[e] : rv[e];
    float4 a = *(const float4*)(Mv + (size_t)s * DDIM + (lane << 2));
    float4 b = *(const float4*)(M  + (size_t)r * DDIM + (lane << 2));
    *(float4*)(out + (size_t)e * DDIM + (lane << 2)) =
        make_float4(a.x - b.x, a.y - b.y, a.z - b.z, a.w - b.w);
}

// ---------------- launch ----------------
extern "C" void kernel_launch(void* const* d_in, const int* in_sizes, int n_in,
                              void* d_out, int out_size)
{
    // Inputs: M, edge_index, rev_index, [dim_size], W1,b1,g1,be1,rm1,rv1,W2,b2,g2,be2,rm2,rv2
    int off = (n_in >= 16) ? 1 : 0;
    const float* M   = (const float*)d_in[0];
    const int*   ei  = (const int*)  d_in[1];
    const int*   rev = (const int*)  d_in[2];
    const float* W1  = (const float*)d_in[3 + off];
    const float* b1  = (const float*)d_in[4 + off];
    const float* g1v = (const float*)d_in[5 + off];
    const float* be1 = (const float*)d_in[6 + off];
    const float* rm1 = (const float*)d_in[7 + off];
    const float* rv1 = (const float*)d_in[8 + off];
    const float* W2  = (const float*)d_in[9 + off];
    const float* b2  = (const float*)d_in[10 + off];
    const float* g2v = (const float*)d_in[11 + off];
    const float* be2 = (const float*)d_in[12 + off];
    const float* rm2 = (const float*)d_in[13 + off];
    const float* rv2 = (const float*)d_in[14 + off];
    float* out = (float*)d_out;

    __half *pAh, *pW1h, *pW2T, *pWcT;
    float  *pBias, *pMvP, *pMv;
    cudaGetSymbolAddress((void**)&pAh,   g_Ah);
    cudaGetSymbolAddress((void**)&pW1h,  g_W1h);
    cudaGetSymbolAddress((void**)&pW2T,  g_W2T);
    cudaGetSymbolAddress((void**)&pWcT,  g_WcT);
    cudaGetSymbolAddress((void**)&pBias, g_bias);
    cudaGetSymbolAddress((void**)&pMvP,  g_MvP);
    cudaGetSymbolAddress((void**)&pMv,   g_Mv);

    static cudaStream_t s1 = nullptr;
    static cudaEvent_t evFork = nullptr, evA = nullptr, evC = nullptr, ev1 = nullptr;
    if (!s1) {
        cudaStreamCreateWithFlags(&s1, cudaStreamNonBlocking);
        cudaEventCreateWithFlags(&evFork, cudaEventDisableTiming);
        cudaEventCreateWithFlags(&evA,    cudaEventDisableTiming);
        cudaEventCreateWithFlags(&evC,    cudaEventDisableTiming);
        cudaEventCreateWithFlags(&ev1,    cudaEventDisableTiming);
    }

    constexpr int SMEM = 3 * (64 + 128) * 72 * 2;   // 82,944 B (<64,128> tiles)
    cudaFuncSetAttribute((const void*)gemm_f16_kernel<64, 128, 0>,
                         cudaFuncAttributeMaxDynamicSharedMemorySize, SMEM);
    cudaFuncSetAttribute((const void*)gemm_f16_kernel<64, 128, 2>,
                         cudaFuncAttributeMaxDynamicSharedMemorySize, SMEM);

    // ---- fork ----
    cudaEventRecord(evFork, 0);
    cudaStreamWaitEvent(s1, evFork, 0);

    // s0: convert M -> fp16 (dominant prep, 164MB read)
    conv_f16_kernel<<<2048, 256>>>(M, pAh, NNODES * KDIM / 4);
    cudaEventRecord(evA, 0);

    // s1: weight pipeline -> WcT
    conv_f16_kernel<<<512, 256, 0, s1>>>(W1, pW1h, KDIM * HDIM / 4);
    fold_w2t_kernel<<<dim3(HDIM / 32, DDIM / 32), dim3(32, 8), 0, s1>>>(
        W2, g1v, rv1, g2v, rv2, pW2T);
    fold_bias_kernel<<<DDIM, 256, 0, s1>>>(
        W2, b1, g1v, be1, rm1, rv1, b2, g2v, be2, rm2, rv2, pBias);
    // combine: WcT[128,4096] = W2T[128,1024] @ W1h[4096,1024]^T  (fp16 out)
    gemm_f16_kernel<64, 128, 0>
        <<<dim3(KDIM / 128, DDIM / 64), 256, SMEM, s1>>>(
            pW2T, HDIM, pW1h, HDIM, pWcT, KDIM, 0, DDIM, HDIM, nullptr, 0);
    cudaEventRecord(evC, s1);

    // s1: main GEMM z=1 (needs Ah)
    cudaStreamWaitEvent(s1, evA, 0);
    gemm_f16_kernel<64, 128, 2>
        <<<dim3(1, (NNODES + 63) / 64), 256, SMEM, s1>>>(
            pAh, KDIM, pWcT, KDIM, pMvP, DDIM, 0, NNODES, KDIM / 2, nullptr, 1);
    cudaEventRecord(ev1, s1);

    // s0: main GEMM z=0 (needs WcT)
    cudaStreamWaitEvent(0, evC, 0);
    gemm_f16_kernel<64, 128, 2>
        <<<dim3(1, (NNODES + 63) / 64), 256, SMEM>>>(
            pAh, KDIM, pWcT, KDIM, pMvP, DDIM, 0, NNODES, KDIM / 2, nullptr, 0);

    // join, then reduce + bias + relu
    cudaStreamWaitEvent(0, ev1, 0);
    reduce_bias_relu_kernel<<<1280, 256>>>(pMvP, pBias, pMv);

    // out[e] = Mv[src[e]] - M[rev[e]]
    scatter_kernel<<<EEDGES / 8, 256>>>(pMv, M, ei, rev, out);
}

// round 17
// speedup vs baseline: 2.6220x; 1.2251x over previous
#include <cuda_runtime.h>
#include <cuda_fp16.h>
#include <cstdint>

// Problem constants (fixed by setup_inputs)
#define NNODES 10000
#define EEDGES 320000
#define DDIM   128
#define HDIM   1024
#define KDIM   4096     // 32 * 128 (only first half of W1 rows matter)

// ---------------- scratch (no allocation allowed) ----------------
// MLP = relu(x @ Wc + bc), Wc = W1[:4096] @ (a1*W2*a2). The main GEMM reads
// fp32 M directly (register-staged fp16 conversion) - no conv pass.
__device__ __align__(128) __half g_W1h[KDIM * HDIM];        // fp16(W1[:4096])  8 MB
__device__ __align__(128) __half g_W2T[DDIM * HDIM];        // fp16((a1*W2*a2)^T) [128][1024]
__device__ __align__(128) __half g_WcT[DDIM * KDIM];        // fp16(Wc^T) [128][4096] 1 MB
__device__ __align__(128) float  g_bias[DDIM];
__device__ __align__(128) float  g_MvP[2 * NNODES * DDIM];  // split-K fp32 partials 10 MB
__device__ __align__(128) float  g_Mv [NNODES * DDIM];

// ---------------- helpers ----------------
__device__ __forceinline__ uint32_t smem_u32(const void* p) {
    uint32_t a;
    asm("{ .reg .u64 t; cvta.to.shared.u64 t, %1; cvt.u32.u64 %0, t; }" : "=r"(a) : "l"(p));
    return a;
}

__device__ __forceinline__ void cp_async16(uint32_t dst, const void* src) {
    asm volatile("cp.async.cg.shared.global [%0], [%1], 16;" :: "r"(dst), "l"(src) : "memory");
}
__device__ __forceinline__ void cp_commit() {
    asm volatile("cp.async.commit_group;" ::: "memory");
}
template<int N>
__device__ __forceinline__ void cp_wait() {
    asm volatile("cp.async.wait_group %0;" :: "n"(N) : "memory");
}

__device__ __forceinline__ void ldmx4(unsigned& r0, unsigned& r1, unsigned& r2, unsigned& r3,
                                      uint32_t addr) {
    asm volatile("ldmatrix.sync.aligned.m8n8.x4.shared.b16 {%0,%1,%2,%3}, [%4];"
                 : "=r"(r0), "=r"(r1), "=r"(r2), "=r"(r3) : "r"(addr));
}

__device__ __forceinline__ void mma_f16(float c[4], const unsigned a[4], const unsigned b[2]) {
    asm volatile(
        "mma.sync.aligned.m16n8k16.row.col.f32.f16.f16.f32 "
        "{%0,%1,%2,%3}, {%4,%5,%6,%7}, {%8,%9}, {%0,%1,%2,%3};\n"
        : "+f"(c[0]), "+f"(c[1]), "+f"(c[2]), "+f"(c[3])
        : "r"(a[0]), "r"(a[1]), "r"(a[2]), "r"(a[3]),
          "r"(b[0]), "r"(b[1]));
}

// ---------------- prep kernels ----------------
__global__ void conv_f16_kernel(const float* __restrict__ in, __half* __restrict__ out, int n4)
{
    int stride = gridDim.x * blockDim.x;
    for (int i = blockIdx.x * blockDim.x + threadIdx.x; i < n4; i += stride) {
        float4 v = ((const float4*)in)[i];
        __half2 h0 = __floats2half2_rn(v.x, v.y);
        __half2 h1 = __floats2half2_rn(v.z, v.w);
        uint2 u = make_uint2(*reinterpret_cast<unsigned*>(&h0),
                             *reinterpret_cast<unsigned*>(&h1));
        ((uint2*)out)[i] = u;
    }
}

// W2 [1024,128] f32 -> W2T [128][1024] fp16, scaled by a1[h]*a2[d]
__global__ void fold_w2t_kernel(const float* __restrict__ W2,
                                const float* __restrict__ g1, const float* __restrict__ rv1,
                                const float* __restrict__ g2, const float* __restrict__ rv2,
                                __half* __restrict__ W2T)
{
    __shared__ float t[32][33];
    int h0 = blockIdx.x * 32, d0 = blockIdx.y * 32;
    int tx = threadIdx.x, ty = threadIdx.y;
    #pragma unroll
    for (int i = 0; i < 4; i++)
        t[ty + i * 8][tx] = W2[(size_t)(h0 + ty + i * 8) * DDIM + d0 + tx];
    __syncthreads();
    float a1 = g1[h0 + tx] * rsqrtf(rv1[h0 + tx] + 1e-5f);
    #pragma unroll
    for (int i = 0; i < 4; i++) {
        int d = d0 + ty + i * 8;
        float a2 = g2[d] * rsqrtf(rv2[d] + 1e-5f);
        W2T[(size_t)d * HDIM + h0 + tx] = __float2half_rn(a1 * a2 * t[tx][ty + i * 8]);
    }
}

// parallel bias fold: one block per d, 256-thread reduction over h
__global__ void fold_bias_kernel(const float* __restrict__ W2,
                                 const float* __restrict__ b1, const float* __restrict__ g1,
                                 const float* __restrict__ be1, const float* __restrict__ rm1,
                                 const float* __restrict__ rv1,
                                 const float* __restrict__ b2, const float* __restrict__ g2,
                                 const float* __restrict__ be2, const float* __restrict__ rm2,
                                 const float* __restrict__ rv2,
                                 float* __restrict__ biasOut)
{
    __shared__ float red[8];
    int d = blockIdx.x;
    int tid = threadIdx.x;
    float s = 0.f;
    for (int h = tid; h < HDIM; h += 256) {
        float a1 = g1[h] * rsqrtf(rv1[h] + 1e-5f);
        float c1 = (b1[h] - rm1[h]) * a1 + be1[h];
        s += c1 * W2[h * DDIM + d];
    }
    #pragma unroll
    for (int o = 16; o > 0; o >>= 1) s += __shfl_down_sync(0xffffffffu, s, o);
    if ((tid & 31) == 0) red[tid >> 5] = s;
    __syncthreads();
    if (tid == 0) {
        float t = 0.f;
        #pragma unroll
        for (int i = 0; i < 8; i++) t += red[i];
        float a2 = g2[d] * rsqrtf(rv2[d] + 1e-5f);
        biasOut[d] = (t + b2[d] - rm2[d]) * a2 + be2[d];
    }
}

// split-K reduce + bias + relu: Mv = relu(p0 + p1 + bias[col])  (fp32)
__global__ void reduce_bias_relu_kernel(const float* __restrict__ p,
                                        const float* __restrict__ bias,
                                        float* __restrict__ out)
{
    constexpr int N4 = NNODES * DDIM / 4;
    int stride = gridDim.x * blockDim.x;
    for (int i = blockIdx.x * blockDim.x + threadIdx.x; i < N4; i += stride) {
        float4 a = ((const float4*)p)[i];
        float4 b = ((const float4*)p)[i + N4];
        float4 bs = ((const float4*)bias)[i & 31];   // DDIM/4 = 32 chunks per row
        float4 r;
        r.x = fmaxf(a.x + b.x + bs.x, 0.f);
        r.y = fmaxf(a.y + b.y + bs.y, 0.f);
        r.z = fmaxf(a.z + b.z + bs.z, 0.f);
        r.w = fmaxf(a.w + b.w + bs.w, 0.f);
        ((float4*)out)[i] = r;
    }
}

// ---------------- combine GEMM: fp16 cp.async + ldmatrix (R10 mainloop) -----
// C[M,:] = A[M,:kLen] @ B[:,:kLen]^T, all fp16 (EPI=0 fp16 out).
__global__ void __launch_bounds__(256, 2)
gemm_f16_kernel(const __half* __restrict__ A, int lda,
                const __half* __restrict__ B, int ldb,
                __half* __restrict__ C, int ldc,
                int Mrows, int kLen)
{
    constexpr int BM = 64, BN = 128;
    constexpr int KT = 64, STAGES = 3;
    constexpr int WM = BM / 2, WN = BN / 4;
    constexpr int MT = WM / 16, NTN = WN / 8;
    constexpr int LDH = KT + 8;
    constexpr int A_HL = BM * LDH;
    constexpr int B_HL = BN * LDH;
    constexpr int ACH = BM * (KT / 8);
    constexpr int BCH = BN * (KT / 8);

    extern __shared__ __align__(16) __half smem[];
    __half* As = smem;
    __half* Bs = smem + STAGES * A_HL;
    const uint32_t asb = smem_u32(As);
    const uint32_t bsb = smem_u32(Bs);

    const int tid   = threadIdx.x;
    const int lane  = tid & 31;
    const int warp  = tid >> 5;
    const int warpM = warp >> 2;
    const int warpN = warp & 3;
    const int bM = blockIdx.y * BM;
    const int bN = blockIdx.x * BN;
    const int NT = kLen / KT;

    const int aRow = lane & 15;
    const int aK   = (lane >> 4) << 3;
    const int bRow = (lane & 7) + ((lane >> 4) << 3);
    const int bK   = ((lane >> 3) & 1) << 3;

    float acc[MT][NTN][4];
    #pragma unroll
    for (int i = 0; i < MT; i++)
        #pragma unroll
        for (int j = 0; j < NTN; j++)
            #pragma unroll
            for (int k = 0; k < 4; k++) acc[i][j][k] = 0.f;

    auto load_stage = [&](int s, int kt) {
        const uint32_t aDst = asb + s * A_HL * 2;
        #pragma unroll
        for (int i = 0; i < ACH / 256; i++) {
            int idx = tid + i * 256;
            int row = idx >> 3;
            int c   = idx & 7;
            int gr  = bM + row; if (gr >= Mrows) gr = Mrows - 1;
            cp_async16(aDst + (row * LDH + c * 8) * 2,
                       A + (size_t)gr * lda + kt * KT + c * 8);
        }
        const uint32_t bDst = bsb + s * B_HL * 2;
        #pragma unroll
        for (int i = 0; i < BCH / 256; i++) {
            int idx = tid + i * 256;
            int row = idx >> 3;
            int c   = idx & 7;
            cp_async16(bDst + (row * LDH + c * 8) * 2,
                       B + (size_t)(bN + row) * ldb + kt * KT + c * 8);
        }
    };

    load_stage(0, 0); cp_commit();
    load_stage(1, 1); cp_commit();

    int s = 0;
    for (int kt = 0; kt < NT; kt++) {
        cp_wait<STAGES - 2>();
        __syncthreads();
        if (kt + 2 < NT)
            load_stage((s + 2 >= STAGES) ? s - 1 : s + 2, kt + 2);
        cp_commit();

        const uint32_t aBase = asb + s * A_HL * 2;
        const uint32_t bBase = bsb + s * B_HL * 2;
        #pragma unroll
        for (int kk = 0; kk < KT / 16; kk++) {
            const int k0 = kk * 16;
            unsigned af[MT][4];
            #pragma unroll
            for (int mt = 0; mt < MT; mt++) {
                uint32_t ad = aBase + ((warpM * WM + mt * 16 + aRow) * LDH + k0 + aK) * 2;
                ldmx4(af[mt][0], af[mt][1], af[mt][2], af[mt][3], ad);
            }
            unsigned bf[NTN][2];
            #pragma unroll
            for (int pr = 0; pr < NTN / 2; pr++) {
                uint32_t bd = bBase + ((warpN * WN + pr * 16 + bRow) * LDH + k0 + bK) * 2;
                unsigned r0, r1, r2, r3;
                ldmx4(r0, r1, r2, r3, bd);
                bf[pr * 2][0] = r0; bf[pr * 2][1] = r1;
                bf[pr * 2 + 1][0] = r2; bf[pr * 2 + 1][1] = r3;
            }
            #pragma unroll
            for (int mt = 0; mt < MT; mt++)
                #pragma unroll
                for (int nt = 0; nt < NTN; nt++)
                    mma_f16(acc[mt][nt], af[mt], bf[nt]);
        }
        if (++s == STAGES) s = 0;
    }

    #pragma unroll
    for (int mt = 0; mt < MT; mt++) {
        int rowBase = bM + warpM * WM + mt * 16 + (lane >> 2);
        #pragma unroll
        for (int half = 0; half < 2; half++) {
            int row = rowBase + half * 8;
            if (row >= Mrows) continue;
            #pragma unroll
            for (int nt = 0; nt < NTN; nt++) {
                int col = bN + warpN * WN + nt * 8 + ((lane & 3) << 1);
                __half2 h = __floats2half2_rn(acc[mt][nt][half * 2 + 0],
                                              acc[mt][nt][half * 2 + 1]);
                *(__half2*)(C + (size_t)row * ldc + col) = h;
            }
        }
    }
}

// ---------------- main GEMM: fused fp32->fp16 A, fp16 B ---------------------
// P[zsel][M,128] = fp16(Afp32[M, zsel*kLen : ...]) @ WcT[:, zsel*kLen : ...]^T
// BM=64, BN=128, KT=64, 256 threads (8 warps 2Mx4N), 3 stages.
// A: LDG.128 fp32 -> regs -> cvt -> STS fp16, two-iteration lookahead.
// B: cp.async; group committed EVERY iteration (tail-safe wait<1>).
// Single leading barrier per iteration orders STS visibility + buffer reuse.
__global__ void __launch_bounds__(256, 2)
gemm_fused_kernel(const float* __restrict__ A, int lda,
                  const __half* __restrict__ B, int ldb,
                  float* __restrict__ P, int Mrows, int kLen, int zsel)
{
    constexpr int BM = 64, BN = 128;
    constexpr int KT = 64, STAGES = 3;
    constexpr int WM = 32, WN = 32;
    constexpr int MT = 2, NTN = 4;
    constexpr int LDH = KT + 8;                    // 72 halves per smem row
    constexpr int A_HL = BM * LDH;
    constexpr int B_HL = BN * LDH;
    constexpr int BCH = BN * (KT / 8);
    constexpr int ACH32 = BM * (KT / 4);           // 1024 float4 chunks per A stage

    extern __shared__ __align__(16) __half smem[];
    __half* As = smem;
    __half* Bs = smem + STAGES * A_HL;
    const uint32_t asb = smem_u32(As);
    const uint32_t bsb = smem_u32(Bs);

    const int tid   = threadIdx.x;
    const int lane  = tid & 31;
    const int warp  = tid >> 5;
    const int warpM = warp >> 2;
    const int warpN = warp & 3;
    const int bM = blockIdx.y * BM;
    const int NT = kLen / KT;

    const float*  Ap = A + (size_t)zsel * kLen;
    const __half* Bp = B + (size_t)zsel * kLen;

    const int aRow = lane & 15;
    const int aK   = (lane >> 4) << 3;
    const int bRow = (lane & 7) + ((lane >> 4) << 3);
    const int bK   = ((lane >> 3) & 1) << 3;

    // A staging: 4 float4 per thread per k-tile. 16 chunks per row.
    const float* aPtr[4];
    uint32_t aSts[4];
    #pragma unroll
    for (int i = 0; i < 4; i++) {
        int idx = tid + i * 256;
        int row = idx >> 4;
        int c   = idx & 15;
        int gr  = bM + row; if (gr >= Mrows) gr = Mrows - 1;
        aPtr[i] = Ap + (size_t)gr * lda + c * 4;
        aSts[i] = (row * LDH + c * 4) * 2;         // bytes within a stage
    }
    float4 areg[4];

    auto ldgA = [&](int kt) {
        #pragma unroll
        for (int i = 0; i < 4; i++)
            areg[i] = *(const float4*)(aPtr[i] + kt * KT);
    };
    auto stsA = [&](int s) {
        const uint32_t base = asb + s * A_HL * 2;
        #pragma unroll
        for (int i = 0; i < 4; i++) {
            __half2 h0 = __floats2half2_rn(areg[i].x, areg[i].y);
            __half2 h1 = __floats2half2_rn(areg[i].z, areg[i].w);
            asm volatile("st.shared.v2.b32 [%0], {%1, %2};"
                         :: "r"(base + aSts[i]),
                            "r"(*reinterpret_cast<unsigned*>(&h0)),
                            "r"(*reinterpret_cast<unsigned*>(&h1)) : "memory");
        }
    };
    auto loadB = [&](int s, int kt) {
        const uint32_t bDst = bsb + s * B_HL * 2;
        #pragma unroll
        for (int i = 0; i < BCH / 256; i++) {
            int idx = tid + i * 256;
            int row = idx >> 3;
            int c   = idx & 7;
            cp_async16(bDst + (row * LDH + c * 8) * 2,
                       Bp + (size_t)row * ldb + kt * KT + c * 8);
        }
    };

    float acc[MT][NTN][4];
    #pragma unroll
    for (int i = 0; i < MT; i++)
        #pragma unroll
        for (int j = 0; j < NTN; j++)
            #pragma unroll
            for (int k = 0; k < 4; k++) acc[i][j][k] = 0.f;

    // prologue
    ldgA(0); stsA(0);
    ldgA(1); stsA(1);
    ldgA(2);
    loadB(0, 0); cp_commit();
    loadB(1, 1); cp_commit();
    __syncthreads();   // STS of stages 0,1 visible

    int s = 0;
    for (int kt = 0; kt < NT; kt++) {
        cp_wait<STAGES - 2>();
        __syncthreads();   // B stage s landed; all warps done reading stage s+2

        const int sN = (s + 2 >= STAGES) ? s - 1 : s + 2;
        if (kt + 2 < NT) {
            stsA(sN);                          // regs hold A(kt+2)
            if (kt + 3 < NT) ldgA(kt + 3);
            loadB(sN, kt + 2);
        }
        cp_commit();                           // always (tail-safe)

        const uint32_t aBase = asb + s * A_HL * 2;
        const uint32_t bBase = bsb + s * B_HL * 2;
        #pragma unroll
        for (int kk = 0; kk < KT / 16; kk++) {
            const int k0 = kk * 16;
            unsigned af[MT][4];
            #pragma unroll
            for (int mt = 0; mt < MT; mt++) {
                uint32_t ad = aBase + ((warpM * WM + mt * 16 + aRow) * LDH + k0 + aK) * 2;
                ldmx4(af[mt][0], af[mt][1], af[mt][2], af[mt][3], ad);
            }
            unsigned bf[NTN][2];
            #pragma unroll
            for (int pr = 0; pr < NTN / 2; pr++) {
                uint32_t bd = bBase + ((warpN * WN + pr * 16 + bRow) * LDH + k0 + bK) * 2;
                unsigned r0, r1, r2, r3;
                ldmx4(r0, r1, r2, r3, bd);
                bf[pr * 2][0] = r0; bf[pr * 2][1] = r1;
                bf[pr * 2 + 1][0] = r2; bf[pr * 2 + 1][1] = r3;
            }
            #pragma unroll
            for (int mt = 0; mt < MT; mt++)
                #pragma unroll
                for (int nt = 0; nt < NTN; nt++)
                    mma_f16(acc[mt][nt], af[mt], bf[nt]);
        }
        if (++s == STAGES) s = 0;
    }

    // epilogue: fp32 partials at P + zsel*Mrows*DDIM
    float* Cp = P + (size_t)zsel * Mrows * DDIM;
    #pragma unroll
    for (int mt = 0; mt < MT; mt++) {
        int rowBase = bM + warpM * WM + mt * 16 + (lane >> 2);
        #pragma unroll
        for (int half = 0; half < 2; half++) {
            int row = rowBase + half * 8;
            if (row >= Mrows) continue;
            #pragma unroll
            for (int nt = 0; nt < NTN; nt++) {
                int col = warpN * WN + nt * 8 + ((lane & 3) << 1);
                *(float2*)(Cp + (size_t)row * DDIM + col) =
                    make_float2(acc[mt][nt][half * 2 + 0], acc[mt][nt][half * 2 + 1]);
            }
        }
    }
}

// ---------------- scatter: out[e] = Mv[src[e]] - M[rev[e]] ----------------
__global__ void scatter_kernel(const float* __restrict__ Mv, const float* __restrict__ M,
                               const int* __restrict__ ei, const int* __restrict__ rv,
                               float* __restrict__ out)
{
    const bool ei64 = ((ei[1] | ei[3] | ei[5] | ei[7]) == 0);
    const bool rv64 = ((rv[1] | rv[3] | rv[5] | rv[7]) == 0);
    int e = blockIdx.x * 8 + (threadIdx.x >> 5);
    if (e >= EEDGES) return;
    int lane = threadIdx.x & 31;
    int s = ei64 ? (int)((const long long*)ei)[e] : ei[e];
    int r = rv64 ? (int)((const long long*)rv)[e] : rv[e];
    float4 a = *(const float4*)(Mv + (size_t)s * DDIM + (lane << 2));
    float4 b = *(const float4*)(M  + (size_t)r * DDIM + (lane << 2));
    *(float4*)(out + (size_t)e * DDIM + (lane << 2)) =
        make_float4(a.x - b.x, a.y - b.y, a.z - b.z, a.w - b.w);
}

// ---------------- launch ----------------
extern "C" void kernel_launch(void* const* d_in, const int* in_sizes, int n_in,
                              void* d_out, int out_size)
{
    // Inputs: M, edge_index, rev_index, [dim_size], W1,b1,g1,be1,rm1,rv1,W2,b2,g2,be2,rm2,rv2
    int off = (n_in >= 16) ? 1 : 0;
    const float* M   = (const float*)d_in[0];
    const int*   ei  = (const int*)  d_in[1];
    const int*   rev = (const int*)  d_in[2];
    const float* W1  = (const float*)d_in[3 + off];
    const float* b1  = (const float*)d_in[4 + off];
    const float* g1v = (const float*)d_in[5 + off];
    const float* be1 = (const float*)d_in[6 + off];
    const float* rm1 = (const float*)d_in[7 + off];
    const float* rv1 = (const float*)d_in[8 + off];
    const float* W2  = (const float*)d_in[9 + off];
    const float* b2  = (const float*)d_in[10 + off];
    const float* g2v = (const float*)d_in[11 + off];
    const float* be2 = (const float*)d_in[12 + off];
    const float* rm2 = (const float*)d_in[13 + off];
    const float* rv2 = (const float*)d_in[14 + off];
    float* out = (float*)d_out;

    __half *pW1h, *pW2T, *pWcT;
    float  *pBias, *pMvP, *pMv;
    cudaGetSymbolAddress((void**)&pW1h,  g_W1h);
    cudaGetSymbolAddress((void**)&pW2T,  g_W2T);
    cudaGetSymbolAddress((void**)&pWcT,  g_WcT);
    cudaGetSymbolAddress((void**)&pBias, g_bias);
    cudaGetSymbolAddress((void**)&pMvP,  g_MvP);
    cudaGetSymbolAddress((void**)&pMv,   g_Mv);

    static cudaStream_t s1 = nullptr;
    static cudaEvent_t evFork = nullptr, evC = nullptr, ev1 = nullptr;
    if (!s1) {
        cudaStreamCreateWithFlags(&s1, cudaStreamNonBlocking);
        cudaEventCreateWithFlags(&evFork, cudaEventDisableTiming);
        cudaEventCreateWithFlags(&evC,    cudaEventDisableTiming);
        cudaEventCreateWithFlags(&ev1,    cudaEventDisableTiming);
    }

    constexpr int SMEM = 3 * (64 + 128) * 72 * 2;   // 82,944 B
    cudaFuncSetAttribute((const void*)gemm_f16_kernel,
                         cudaFuncAttributeMaxDynamicSharedMemorySize, SMEM);
    cudaFuncSetAttribute((const void*)gemm_fused_kernel,
                         cudaFuncAttributeMaxDynamicSharedMemorySize, SMEM);

    // ---- fork ----
    cudaEventRecord(evFork, 0);
    cudaStreamWaitEvent(s1, evFork, 0);

    // s1: weight pipeline -> WcT
    conv_f16_kernel<<<512, 256, 0, s1>>>(W1, pW1h, KDIM * HDIM / 4);
    fold_w2t_kernel<<<dim3(HDIM / 32, DDIM / 32), dim3(32, 8), 0, s1>>>(
        W2, g1v, rv1, g2v, rv2, pW2T);
    fold_bias_kernel<<<DDIM, 256, 0, s1>>>(
        W2, b1, g1v, be1, rm1, rv1, b2, g2v, be2, rm2, rv2, pBias);
    // combine: WcT[128,4096] = W2T[128,1024] @ W1h[4096,1024]^T  (fp16 out)
    gemm_f16_kernel<<<dim3(KDIM / 128, DDIM / 64), 256, SMEM, s1>>>(
        pW2T, HDIM, pW1h, HDIM, pWcT, KDIM, DDIM, HDIM);
    cudaEventRecord(evC, s1);

    // s1: main fused GEMM z=1 (reads fp32 M directly)
    gemm_fused_kernel<<<dim3(1, (NNODES + 63) / 64), 256, SMEM, s1>>>(
        M, KDIM, pWcT, KDIM, pMvP, NNODES, KDIM / 2, 1);
    cudaEventRecord(ev1, s1);

    // s0: main fused GEMM z=0 (needs WcT)
    cudaStreamWaitEvent(0, evC, 0);
    gemm_fused_kernel<<<dim3(1, (NNODES + 63) / 64), 256, SMEM>>>(
        M, KDIM, pWcT, KDIM, pMvP, NNODES, KDIM / 2, 0);

    // join, then reduce + bias + relu
    cudaStreamWaitEvent(0, ev1, 0);
    reduce_bias_relu_kernel<<<1280, 256>>>(pMvP, pBias, pMv);

    // out[e] = Mv[src[e]] - M[rev[e]]
    scatter_kernel<<<EEDGES / 8, 256>>>(pMv, M, ei, rev, out);
}